// round 14
// baseline (speedup 1.0000x reference)
#include <cuda_runtime.h>
#include <cuda_bf16.h>
#include <cuda_fp16.h>
#include <cstdint>

// Problem constants
constexpr int N_NODES = 10000;
constexpr int N_EDGES = 100000;
constexpr int WIDTH   = 64;
constexpr int KW      = 1024;
constexpr int KIN     = 6;
constexpr int DEPTH   = 6;

// ---------------------------------------------------------------------------
// Scratch (device globals; no allocations allowed)
// ---------------------------------------------------------------------------
__device__ __half g_h1[(size_t)N_EDGES * KW];                 // 204.8 MB
__device__ __half g_h2[(size_t)N_EDGES * KW];                 // 204.8 MB
__device__ __half g_ew[(size_t)N_EDGES * WIDTH * WIDTH];      // 819.2 MB
__device__ __half g_k2t[KW * KW];                             // k2^T [N][K]
__device__ __half g_k3t[WIDTH * WIDTH * KW];                  // k3^T [N][K]
__device__ float  g_z[N_NODES * WIDTH];
__device__ float  g_zbase[N_NODES * WIDTH];
__device__ float  g_agg[N_NODES * WIDTH];
__device__ float  g_deg[N_NODES];

// ---------------------------------------------------------------------------
// Helpers
// ---------------------------------------------------------------------------
__device__ __forceinline__ void cp16(void* dst, const void* src, bool pred) {
    uint32_t d = (uint32_t)__cvta_generic_to_shared(dst);
    int sz = pred ? 16 : 0;
    asm volatile("cp.async.cg.shared.global [%0], [%1], 16, %2;\n"
                 :: "r"(d), "l"(src), "r"(sz));
}
#define CP_COMMIT() asm volatile("cp.async.commit_group;\n" ::: "memory")

__device__ __forceinline__ void ldsm_x4(uint32_t* r, uint32_t addr) {
    asm volatile("ldmatrix.sync.aligned.m8n8.x4.shared.b16 {%0,%1,%2,%3}, [%4];"
                 : "=r"(r[0]), "=r"(r[1]), "=r"(r[2]), "=r"(r[3]) : "r"(addr));
}

__device__ __forceinline__ void mma_f16(float* c, const uint32_t* a, const uint32_t* b) {
    asm("mma.sync.aligned.m16n8k16.row.col.f32.f16.f16.f32 "
        "{%0,%1,%2,%3}, {%4,%5,%6,%7}, {%8,%9}, {%0,%1,%2,%3};"
        : "+f"(c[0]), "+f"(c[1]), "+f"(c[2]), "+f"(c[3])
        : "r"(a[0]), "r"(a[1]), "r"(a[2]), "r"(a[3]), "r"(b[0]), "r"(b[1]));
}

// streaming (evict-first) 32-bit global store
__device__ __forceinline__ void stg_cs32(void* p, uint32_t v) {
    asm volatile("st.global.cs.b32 [%0], %1;" :: "l"(p), "r"(v) : "memory");
}

// ---------------------------------------------------------------------------
// Weight prep: transpose k2/k3 to [N][K] and convert to half
// ---------------------------------------------------------------------------
__global__ void transpose_h(const float* __restrict__ in, __half* __restrict__ out,
                            int K, int N) {
    __shared__ float t[32][33];
    const int k0 = blockIdx.x * 32, n0 = blockIdx.y * 32;
    const int tx = threadIdx.x, ty = threadIdx.y;   // 32 x 8
    #pragma unroll
    for (int j = 0; j < 32; j += 8)
        t[ty + j][tx] = in[(size_t)(k0 + ty + j) * N + n0 + tx];
    __syncthreads();
    #pragma unroll
    for (int j = 0; j < 32; j += 8)
        out[(size_t)(n0 + ty + j) * K + k0 + tx] = __float2half_rn(t[tx][ty + j]);
}

// ---------------------------------------------------------------------------
// h1 = relu(edge_attr @ k1 + b1), stored half.  K=6 -> SIMT.
// ---------------------------------------------------------------------------
__global__ __launch_bounds__(256) void h1_kernel(const float* __restrict__ ea,
                                                 const float* __restrict__ k1,
                                                 const float* __restrict__ b1) {
    __shared__ float a[16][KIN];
    const int e0 = blockIdx.x * 16;
    const int tid = threadIdx.x;
    if (tid < 16 * KIN) {
        int q = tid / KIN, c = tid % KIN;
        a[q][c] = ea[(long)(e0 + q) * KIN + c];
    }
    __syncthreads();
    #pragma unroll
    for (int jj = 0; jj < 4; jj++) {
        int j = tid + jj * 256;
        float w0 = k1[j],          w1 = k1[KW + j],     w2 = k1[2 * KW + j];
        float w3 = k1[3 * KW + j], w4 = k1[4 * KW + j], w5 = k1[5 * KW + j];
        float bb = b1[j];
        #pragma unroll
        for (int q = 0; q < 16; q++) {
            float s = bb + a[q][0] * w0 + a[q][1] * w1 + a[q][2] * w2
                         + a[q][3] * w3 + a[q][4] * w4 + a[q][5] * w5;
            g_h1[(long)(e0 + q) * KW + j] = __float2half_rn(fmaxf(s, 0.f));
        }
    }
}

// ---------------------------------------------------------------------------
// fp16 tensor-core GEMM, fp32 accumulate. BK=64, 3-stage cp.async ring,
// ONE __syncthreads + ONE wait_group per 64-wide k-tile. (R9 config —
// best measured: 622us for MODE 0.)
//   MODE 0: g_h2 = half(relu(g_h1 @ k2 + b2))   [E,1024]x[1024,1024]
//   MODE 1: g_ew = half(g_h2 @ k3 + b3)         [E,1024]x[1024,4096]
//           (ew stored with st.global.cs: evict-first)
// B pre-transposed [N][K] half. BM=128 BN=128, 8 warps (2x4), warp tile
// 64x32, smem row stride 72 halfs (conflict-free). 2 CTAs/SM.
// ---------------------------------------------------------------------------
constexpr int G_STAGES = 3;
constexpr int G_LDS = 72;                                  // smem row stride (halfs)
constexpr int G_STAGE_HALFS = 128 * G_LDS;                 // 9216 halfs per operand
constexpr int G_SMEM_BYTES = G_STAGES * G_STAGE_HALFS * 2 * 2;  // 110592

template <int MODE>
__global__ __launch_bounds__(256, 2) void gemm_f16(const float* __restrict__ bias) {
    constexpr long M = N_EDGES;
    constexpr int KT = KW / 64;                            // 16 k-tiles
    constexpr int LDS = G_LDS;
    const __half* __restrict__ A  = (MODE == 0) ? g_h1  : g_h2;
    const __half* __restrict__ Bt = (MODE == 0) ? g_k2t : g_k3t;

    extern __shared__ __half dsmem[];
    __half* As = dsmem;                                    // 3 x 9216 halfs
    __half* Bs = dsmem + G_STAGES * G_STAGE_HALFS;

    const int tid  = threadIdx.x;
    const int bn   = blockIdx.x;          // fast-moving: N tile
    const int bm   = blockIdx.y;          // M tile
    const int warp = tid >> 5, lane = tid & 31;
    const int wm   = warp >> 2, wn = warp & 3;      // 2 x 4 warp grid
    const int gid  = lane >> 2, tig = lane & 3;

    float acc[4][4][4];
    #pragma unroll
    for (int i = 0; i < 4; i++)
        #pragma unroll
        for (int j = 0; j < 4; j++)
            #pragma unroll
            for (int r = 0; r < 4; r++) acc[i][j][r] = 0.f;

    // loaders: per operand per stage: 128 rows x 8 chunks(16B), 256 thr -> 4 each
    const int lr0 = tid >> 2;             // 0..63
    const int lc0 = (tid & 3) * 2;        // 0,2,4,6

    const uint32_t sA = (uint32_t)__cvta_generic_to_shared(As);
    const uint32_t sB = (uint32_t)__cvta_generic_to_shared(Bs);

    // ldmatrix lane addressing
    const int a_row = wm * 64 + (lane & 15);
    const int a_kc  = (lane >> 4) * 8;
    const int b_row = wn * 32 + (lane & 7) + ((lane >> 4) & 1) * 8;
    const int b_kc  = ((lane >> 3) & 1) * 8;

    const long m0 = (long)bm * 128;
    const long arow0 = m0 + lr0;
    const long arow1 = m0 + lr0 + 64;
    const bool pa0 = arow0 < M, pa1 = arow1 < M;
    const __half* gA0 = A + arow0 * KW;
    const __half* gA1 = A + arow1 * KW;
    const __half* gB0 = Bt + ((long)bn * 128 + lr0) * KW;
    const __half* gB1 = Bt + ((long)bn * 128 + lr0 + 64) * KW;
    __half* wA0 = As + lr0 * LDS;
    __half* wA1 = As + (lr0 + 64) * LDS;
    __half* wB0 = Bs + lr0 * LDS;
    __half* wB1 = Bs + (lr0 + 64) * LDS;

    auto load_stage = [&](int s, int kt) {
        const int so = s * G_STAGE_HALFS;
        const int kb = kt * 64;
        #pragma unroll
        for (int j = 0; j < 2; j++) {
            int c = (lc0 + j) * 8;
            cp16(wA0 + so + c, gA0 + kb + c, pa0);
            cp16(wA1 + so + c, gA1 + kb + c, pa1);
            cp16(wB0 + so + c, gB0 + kb + c, true);
            cp16(wB1 + so + c, gB1 + kb + c, true);
        }
    };

    // prologue: stages 0,1
    load_stage(0, 0); CP_COMMIT();
    load_stage(1, 1); CP_COMMIT();

    int cur = 0, nxt = 2;   // slot of kt, slot for kt+2
    for (int kt = 0; kt < KT; kt++) {
        asm volatile("cp.async.wait_group 1;" ::: "memory");
        __syncthreads();

        // load kt+2 into slot (kt+2)%3 == (kt-1)%3, freed by the barrier
        const int ld_kt = kt + 2;
        if (ld_kt < KT) load_stage(nxt, ld_kt);
        CP_COMMIT();

        const uint32_t baseA = sA + cur * (G_STAGE_HALFS * 2);
        const uint32_t baseB = sB + cur * (G_STAGE_HALFS * 2);
        #pragma unroll
        for (int ks = 0; ks < 4; ks++) {
            uint32_t af[4][4], bf[4][2];
            #pragma unroll
            for (int mi = 0; mi < 4; mi++) {
                uint32_t ad = baseA + 2 * ((a_row + mi * 16) * LDS + ks * 16 + a_kc);
                ldsm_x4(af[mi], ad);
            }
            #pragma unroll
            for (int pp = 0; pp < 2; pp++) {
                uint32_t r[4];
                uint32_t bd = baseB + 2 * ((b_row + pp * 16) * LDS + ks * 16 + b_kc);
                ldsm_x4(r, bd);
                bf[pp * 2][0] = r[0]; bf[pp * 2][1] = r[1];
                bf[pp * 2 + 1][0] = r[2]; bf[pp * 2 + 1][1] = r[3];
            }
            #pragma unroll
            for (int mi = 0; mi < 4; mi++)
                #pragma unroll
                for (int ni = 0; ni < 4; ni++)
                    mma_f16(acc[mi][ni], af[mi], bf[ni]);
        }
        cur = (cur == 2) ? 0 : cur + 1;
        nxt = (nxt == 2) ? 0 : nxt + 1;
    }

    // epilogue (c-frag: rows gid, gid+8; cols 2*tig, 2*tig+1)
    #pragma unroll
    for (int mi = 0; mi < 4; mi++) {
        long r0 = m0 + wm * 64 + mi * 16 + gid;
        #pragma unroll
        for (int ni = 0; ni < 4; ni++) {
            int c0 = bn * 128 + wn * 32 + ni * 8 + tig * 2;
            float bb0 = bias[c0], bb1 = bias[c0 + 1];
            #pragma unroll
            for (int h = 0; h < 2; h++) {
                long r = r0 + h * 8;
                if (r < M) {
                    float v0 = acc[mi][ni][h * 2 + 0] + bb0;
                    float v1 = acc[mi][ni][h * 2 + 1] + bb1;
                    if (MODE == 0) {
                        *reinterpret_cast<__half2*>(&g_h2[r * KW + c0]) =
                            __floats2half2_rn(fmaxf(v0, 0.f), fmaxf(v1, 0.f));
                    } else {
                        __half2 hv = __floats2half2_rn(v0, v1);
                        stg_cs32(&g_ew[r * (size_t)(WIDTH * WIDTH) + c0],
                                 *reinterpret_cast<uint32_t*>(&hv));
                    }
                }
            }
        }
    }
}

// ---------------------------------------------------------------------------
// Degree, z0 init
// ---------------------------------------------------------------------------
__global__ void deg_zero() {
    int i = blockIdx.x * 256 + threadIdx.x;
    if (i < N_NODES) g_deg[i] = 0.f;
}
__global__ void deg_count(const int* __restrict__ dst) {
    int e = blockIdx.x * 256 + threadIdx.x;
    if (e < N_EDGES) atomicAdd(&g_deg[dst[e]], 1.f);
}
__global__ void z0_kernel(const float* __restrict__ x, const float* __restrict__ w,
                          const float* __restrict__ b) {
    int i = blockIdx.x * 256 + threadIdx.x;
    if (i < N_NODES * WIDTH) g_z[i] = x[i >> 6] * w[i & 63] + b[i & 63];
}

// ---------------------------------------------------------------------------
// zbase = z @ root_w + conv_b (also zeroes agg). 4 nodes / 256-thread block.
// ---------------------------------------------------------------------------
__global__ __launch_bounds__(256) void zbase_kernel(const float* __restrict__ rw,
                                                    const float* __restrict__ cb) {
    __shared__ float w[WIDTH * WIDTH];
    __shared__ float zs[4][WIDTH];
    const int tid = threadIdx.x;
    const int n0 = blockIdx.x * 4;
    for (int t = tid; t < WIDTH * WIDTH; t += 256) w[t] = rw[t];
    const int q = tid >> 6, o = tid & 63;
    zs[q][o] = g_z[(n0 + q) * WIDTH + o];
    __syncthreads();
    float s = cb[o];
    #pragma unroll
    for (int i = 0; i < WIDTH; i++) s += zs[q][i] * w[i * WIDTH + o];
    g_zbase[(n0 + q) * WIDTH + o] = s;
    g_agg[(n0 + q) * WIDTH + o] = 0.f;
}

// ---------------------------------------------------------------------------
// Fused: z' = relu(agg/deg + zbase); then zbase' = z' @ root_w + conv_b;
// zero agg for next iteration. Same math/order as update_kernel+zbase_kernel.
// ---------------------------------------------------------------------------
__global__ __launch_bounds__(256) void update_zbase_kernel(const float* __restrict__ rw,
                                                           const float* __restrict__ cb) {
    __shared__ float w[WIDTH * WIDTH];
    __shared__ float zs[4][WIDTH];
    const int tid = threadIdx.x;
    const int n0 = blockIdx.x * 4;
    for (int t = tid; t < WIDTH * WIDTH; t += 256) w[t] = rw[t];
    const int q = tid >> 6, o = tid & 63;
    const int n = n0 + q;
    const float d = fmaxf(g_deg[n], 1.f);
    const float znew = fmaxf(g_agg[n * WIDTH + o] / d + g_zbase[n * WIDTH + o], 0.f);
    g_z[n * WIDTH + o] = znew;
    zs[q][o] = znew;
    __syncthreads();
    float s = cb[o];
    #pragma unroll
    for (int i = 0; i < WIDTH; i++) s += zs[q][i] * w[i * WIDTH + o];
    g_zbase[n * WIDTH + o] = s;
    g_agg[n * WIDTH + o] = 0.f;
}

// ---------------------------------------------------------------------------
// Final z = relu(agg/deg + zbase)
// ---------------------------------------------------------------------------
__global__ void update_kernel() {
    int i = blockIdx.x * 256 + threadIdx.x;
    if (i < N_NODES * WIDTH) {
        float d = fmaxf(g_deg[i >> 6], 1.f);
        g_z[i] = fmaxf(g_agg[i] / d + g_zbase[i], 0.f);
    }
}

// ---------------------------------------------------------------------------
// Message + scatter: one warp per edge. msg = z[src] @ ew[e] (64x64 fp16),
// fp32 accumulate, atomic scatter into agg[dst].
// Zero-skip: SINGLE 64-bit mask with 8-wide chunks (R8 register footprint,
// one ragged chunk per edge instead of two). Ascending 64-bit pop order ==
// half0-then-half1 == R8 accumulation order (bit-exact). __ldcs on the row
// stream: rows are read once per iteration and can't be L2-resident anyway.
// ---------------------------------------------------------------------------
__global__ __launch_bounds__(256) void msg_kernel(const int* __restrict__ src,
                                                  const int* __restrict__ dst) {
    const int e = blockIdx.x * 8 + (threadIdx.x >> 5);
    if (e >= N_EDGES) return;
    const int lane = threadIdx.x & 31;
    const int s = src[e];
    const float z0 = g_z[s * WIDTH + lane];
    const float z1 = g_z[s * WIDTH + 32 + lane];
    const uint32_t b0 = __ballot_sync(0xffffffffu, z0 != 0.f);
    const uint32_t b1 = __ballot_sync(0xffffffffu, z1 != 0.f);
    uint64_t m = ((uint64_t)b1 << 32) | (uint64_t)b0;
    const __half2* row = reinterpret_cast<const __half2*>(g_ew) + (size_t)e * 2048 + lane;
    float a0 = 0.f, a1 = 0.f;

    while (m) {
        int idx[8];
        #pragma unroll
        for (int u = 0; u < 8; u++) {
            if (m) { idx[u] = __ffsll(m) - 1; m &= m - 1; }
            else     idx[u] = -1;
        }
        __half2 w[8];
        #pragma unroll
        for (int u = 0; u < 8; u++)
            if (idx[u] >= 0) w[u] = __ldcs(&row[idx[u] * 32]);
        #pragma unroll
        for (int u = 0; u < 8; u++) {
            if (idx[u] >= 0) {
                const float zsel = (idx[u] < 32) ? z0 : z1;
                const float zi = __shfl_sync(0xffffffffu, zsel, idx[u] & 31);
                const float2 wf = __half22float2(w[u]);
                a0 = fmaf(zi, wf.x, a0);
                a1 = fmaf(zi, wf.y, a1);
            }
        }
    }

    const int d = dst[e];
    atomicAdd(&g_agg[d * WIDTH + lane * 2],     a0);
    atomicAdd(&g_agg[d * WIDTH + lane * 2 + 1], a1);
}

// ---------------------------------------------------------------------------
// out = z @ fc2_w + fc2_b : warp per node
// ---------------------------------------------------------------------------
__global__ __launch_bounds__(256) void out_kernel(const float* __restrict__ w,
                                                  const float* __restrict__ b,
                                                  float* __restrict__ out) {
    const int n = blockIdx.x * 8 + (threadIdx.x >> 5);
    const int lane = threadIdx.x & 31;
    if (n >= N_NODES) return;
    float s = g_z[n * WIDTH + lane] * w[lane] + g_z[n * WIDTH + 32 + lane] * w[32 + lane];
    #pragma unroll
    for (int off = 16; off; off >>= 1) s += __shfl_xor_sync(0xffffffffu, s, off);
    if (lane == 0) out[n] = s + b[0];
}

// ---------------------------------------------------------------------------
// Launch
// ---------------------------------------------------------------------------
extern "C" void kernel_launch(void* const* d_in, const int* in_sizes, int n_in,
                              void* d_out, int out_size) {
    const float* x      = (const float*)d_in[0];
    const int*   ei     = (const int*)  d_in[1];
    const float* ea     = (const float*)d_in[2];
    const float* fc1_w  = (const float*)d_in[3];
    const float* fc1_b  = (const float*)d_in[4];
    const float* k1_w   = (const float*)d_in[5];
    const float* k1_b   = (const float*)d_in[6];
    const float* k2_w   = (const float*)d_in[7];
    const float* k2_b   = (const float*)d_in[8];
    const float* k3_w   = (const float*)d_in[9];
    const float* k3_b   = (const float*)d_in[10];
    const float* root_w = (const float*)d_in[11];
    const float* conv_b = (const float*)d_in[12];
    const float* fc2_w  = (const float*)d_in[13];
    const float* fc2_b  = (const float*)d_in[14];
    const int* src = ei;
    const int* dst = ei + N_EDGES;
    float* out = (float*)d_out;

    __half* k2t_p; cudaGetSymbolAddress((void**)&k2t_p, g_k2t);
    __half* k3t_p; cudaGetSymbolAddress((void**)&k3t_p, g_k3t);

    cudaFuncSetAttribute(gemm_f16<0>, cudaFuncAttributeMaxDynamicSharedMemorySize, G_SMEM_BYTES);
    cudaFuncSetAttribute(gemm_f16<1>, cudaFuncAttributeMaxDynamicSharedMemorySize, G_SMEM_BYTES);

    transpose_h<<<dim3(32, 32),  dim3(32, 8)>>>(k2_w, k2t_p, KW, KW);
    transpose_h<<<dim3(32, 128), dim3(32, 8)>>>(k3_w, k3t_p, KW, WIDTH * WIDTH);
    h1_kernel<<<N_EDGES / 16, 256>>>(ea, k1_w, k1_b);
    gemm_f16<0><<<dim3(KW / 128, (N_EDGES + 127) / 128), 256, G_SMEM_BYTES>>>(k2_b);
    gemm_f16<1><<<dim3((WIDTH * WIDTH) / 128, (N_EDGES + 127) / 128), 256, G_SMEM_BYTES>>>(k3_b);
    deg_zero<<<(N_NODES + 255) / 256, 256>>>();
    deg_count<<<(N_EDGES + 255) / 256, 256>>>(dst);
    z0_kernel<<<(N_NODES * WIDTH) / 256, 256>>>(x, fc1_w, fc1_b);
    zbase_kernel<<<N_NODES / 4, 256>>>(root_w, conv_b);
    for (int it = 0; it < DEPTH; it++) {
        msg_kernel<<<(N_EDGES + 7) / 8, 256>>>(src, dst);
        if (it < DEPTH - 1)
            update_zbase_kernel<<<N_NODES / 4, 256>>>(root_w, conv_b);
        else
            update_kernel<<<(N_NODES * WIDTH) / 256, 256>>>();
    }
    out_kernel<<<(N_NODES + 7) / 8, 256>>>(fc2_w, fc2_b, out);
}

// round 15
// speedup vs baseline: 1.0268x; 1.0268x over previous
#include <cuda_runtime.h>
#include <cuda_bf16.h>
#include <cuda_fp16.h>
#include <cstdint>

// Problem constants
constexpr int N_NODES = 10000;
constexpr int N_EDGES = 100000;
constexpr int WIDTH   = 64;
constexpr int KW      = 1024;
constexpr int KIN     = 6;
constexpr int DEPTH   = 6;

// ---------------------------------------------------------------------------
// Scratch (device globals; no allocations allowed)
// ---------------------------------------------------------------------------
__device__ __half g_h1[(size_t)N_EDGES * KW];                 // 204.8 MB
__device__ __half g_h2[(size_t)N_EDGES * KW];                 // 204.8 MB
__device__ __half g_ew[(size_t)N_EDGES * WIDTH * WIDTH];      // 819.2 MB
__device__ __half g_k2t[KW * KW];                             // k2^T [N][K]
__device__ __half g_k3t[WIDTH * WIDTH * KW];                  // k3^T [N][K]
__device__ float  g_z[N_NODES * WIDTH];
__device__ float  g_zbase[N_NODES * WIDTH];
__device__ float  g_agg[N_NODES * WIDTH];
__device__ float  g_deg[N_NODES];

// ---------------------------------------------------------------------------
// Helpers
// ---------------------------------------------------------------------------
__device__ __forceinline__ void cp16(void* dst, const void* src, bool pred) {
    uint32_t d = (uint32_t)__cvta_generic_to_shared(dst);
    int sz = pred ? 16 : 0;
    asm volatile("cp.async.cg.shared.global [%0], [%1], 16, %2;\n"
                 :: "r"(d), "l"(src), "r"(sz));
}
#define CP_COMMIT() asm volatile("cp.async.commit_group;\n" ::: "memory")

__device__ __forceinline__ void ldsm_x4(uint32_t* r, uint32_t addr) {
    asm volatile("ldmatrix.sync.aligned.m8n8.x4.shared.b16 {%0,%1,%2,%3}, [%4];"
                 : "=r"(r[0]), "=r"(r[1]), "=r"(r[2]), "=r"(r[3]) : "r"(addr));
}

__device__ __forceinline__ void mma_f16(float* c, const uint32_t* a, const uint32_t* b) {
    asm("mma.sync.aligned.m16n8k16.row.col.f32.f16.f16.f32 "
        "{%0,%1,%2,%3}, {%4,%5,%6,%7}, {%8,%9}, {%0,%1,%2,%3};"
        : "+f"(c[0]), "+f"(c[1]), "+f"(c[2]), "+f"(c[3])
        : "r"(a[0]), "r"(a[1]), "r"(a[2]), "r"(a[3]), "r"(b[0]), "r"(b[1]));
}

// streaming (evict-first) 32-bit global store
__device__ __forceinline__ void stg_cs32(void* p, uint32_t v) {
    asm volatile("st.global.cs.b32 [%0], %1;" :: "l"(p), "r"(v) : "memory");
}

// ---------------------------------------------------------------------------
// Weight prep: transpose k2/k3 to [N][K] and convert to half
// ---------------------------------------------------------------------------
__global__ void transpose_h(const float* __restrict__ in, __half* __restrict__ out,
                            int K, int N) {
    __shared__ float t[32][33];
    const int k0 = blockIdx.x * 32, n0 = blockIdx.y * 32;
    const int tx = threadIdx.x, ty = threadIdx.y;   // 32 x 8
    #pragma unroll
    for (int j = 0; j < 32; j += 8)
        t[ty + j][tx] = in[(size_t)(k0 + ty + j) * N + n0 + tx];
    __syncthreads();
    #pragma unroll
    for (int j = 0; j < 32; j += 8)
        out[(size_t)(n0 + ty + j) * K + k0 + tx] = __float2half_rn(t[tx][ty + j]);
}

// ---------------------------------------------------------------------------
// h1 = relu(edge_attr @ k1 + b1), stored half (vectorized half2 stores).
// Each thread computes 2 adjacent columns; same FMA expression as before ->
// bit-identical h1. 16 edges x 1024 cols per block.
// ---------------------------------------------------------------------------
__global__ __launch_bounds__(256) void h1_kernel(const float* __restrict__ ea,
                                                 const float* __restrict__ k1,
                                                 const float* __restrict__ b1) {
    __shared__ float a[16][KIN];
    const int e0 = blockIdx.x * 16;
    const int tid = threadIdx.x;
    if (tid < 16 * KIN) {
        int q = tid / KIN, c = tid % KIN;
        a[q][c] = ea[(long)(e0 + q) * KIN + c];
    }
    __syncthreads();
    #pragma unroll
    for (int jj = 0; jj < 2; jj++) {
        const int j0 = 2 * tid + jj * 512;       // columns j0, j0+1
        float wA[KIN], wB[KIN];
        #pragma unroll
        for (int c = 0; c < KIN; c++) {
            wA[c] = k1[c * KW + j0];
            wB[c] = k1[c * KW + j0 + 1];
        }
        const float bA = b1[j0], bB = b1[j0 + 1];
        #pragma unroll
        for (int q = 0; q < 16; q++) {
            float sA = bA + a[q][0] * wA[0] + a[q][1] * wA[1] + a[q][2] * wA[2]
                          + a[q][3] * wA[3] + a[q][4] * wA[4] + a[q][5] * wA[5];
            float sB = bB + a[q][0] * wB[0] + a[q][1] * wB[1] + a[q][2] * wB[2]
                          + a[q][3] * wB[3] + a[q][4] * wB[4] + a[q][5] * wB[5];
            *reinterpret_cast<__half2*>(&g_h1[(long)(e0 + q) * KW + j0]) =
                __halves2half2(__float2half_rn(fmaxf(sA, 0.f)),
                               __float2half_rn(fmaxf(sB, 0.f)));
        }
    }
}

// ---------------------------------------------------------------------------
// fp16 tensor-core GEMM, fp32 accumulate. BK=64, 3-stage cp.async ring,
// ONE __syncthreads + ONE wait_group per 64-wide k-tile. (R9 config —
// best measured: 622us for MODE 0. Tensor pipe pinned at ~55% across five
// schedule variants -> legacy mma.sync hardware ceiling, do not re-tune.)
//   MODE 0: g_h2 = half(relu(g_h1 @ k2 + b2))   [E,1024]x[1024,1024]
//   MODE 1: g_ew = half(g_h2 @ k3 + b3)         [E,1024]x[1024,4096]
//           (ew stored with st.global.cs: evict-first)
// B pre-transposed [N][K] half. BM=128 BN=128, 8 warps (2x4), warp tile
// 64x32, smem row stride 72 halfs (conflict-free). 2 CTAs/SM.
// ---------------------------------------------------------------------------
constexpr int G_STAGES = 3;
constexpr int G_LDS = 72;                                  // smem row stride (halfs)
constexpr int G_STAGE_HALFS = 128 * G_LDS;                 // 9216 halfs per operand
constexpr int G_SMEM_BYTES = G_STAGES * G_STAGE_HALFS * 2 * 2;  // 110592

template <int MODE>
__global__ __launch_bounds__(256, 2) void gemm_f16(const float* __restrict__ bias) {
    constexpr long M = N_EDGES;
    constexpr int KT = KW / 64;                            // 16 k-tiles
    constexpr int LDS = G_LDS;
    const __half* __restrict__ A  = (MODE == 0) ? g_h1  : g_h2;
    const __half* __restrict__ Bt = (MODE == 0) ? g_k2t : g_k3t;

    extern __shared__ __half dsmem[];
    __half* As = dsmem;                                    // 3 x 9216 halfs
    __half* Bs = dsmem + G_STAGES * G_STAGE_HALFS;

    const int tid  = threadIdx.x;
    const int bn   = blockIdx.x;          // fast-moving: N tile
    const int bm   = blockIdx.y;          // M tile
    const int warp = tid >> 5, lane = tid & 31;
    const int wm   = warp >> 2, wn = warp & 3;      // 2 x 4 warp grid
    const int gid  = lane >> 2, tig = lane & 3;

    float acc[4][4][4];
    #pragma unroll
    for (int i = 0; i < 4; i++)
        #pragma unroll
        for (int j = 0; j < 4; j++)
            #pragma unroll
            for (int r = 0; r < 4; r++) acc[i][j][r] = 0.f;

    // loaders: per operand per stage: 128 rows x 8 chunks(16B), 256 thr -> 4 each
    const int lr0 = tid >> 2;             // 0..63
    const int lc0 = (tid & 3) * 2;        // 0,2,4,6

    const uint32_t sA = (uint32_t)__cvta_generic_to_shared(As);
    const uint32_t sB = (uint32_t)__cvta_generic_to_shared(Bs);

    // ldmatrix lane addressing
    const int a_row = wm * 64 + (lane & 15);
    const int a_kc  = (lane >> 4) * 8;
    const int b_row = wn * 32 + (lane & 7) + ((lane >> 4) & 1) * 8;
    const int b_kc  = ((lane >> 3) & 1) * 8;

    const long m0 = (long)bm * 128;
    const long arow0 = m0 + lr0;
    const long arow1 = m0 + lr0 + 64;
    const bool pa0 = arow0 < M, pa1 = arow1 < M;
    const __half* gA0 = A + arow0 * KW;
    const __half* gA1 = A + arow1 * KW;
    const __half* gB0 = Bt + ((long)bn * 128 + lr0) * KW;
    const __half* gB1 = Bt + ((long)bn * 128 + lr0 + 64) * KW;
    __half* wA0 = As + lr0 * LDS;
    __half* wA1 = As + (lr0 + 64) * LDS;
    __half* wB0 = Bs + lr0 * LDS;
    __half* wB1 = Bs + (lr0 + 64) * LDS;

    auto load_stage = [&](int s, int kt) {
        const int so = s * G_STAGE_HALFS;
        const int kb = kt * 64;
        #pragma unroll
        for (int j = 0; j < 2; j++) {
            int c = (lc0 + j) * 8;
            cp16(wA0 + so + c, gA0 + kb + c, pa0);
            cp16(wA1 + so + c, gA1 + kb + c, pa1);
            cp16(wB0 + so + c, gB0 + kb + c, true);
            cp16(wB1 + so + c, gB1 + kb + c, true);
        }
    };

    // prologue: stages 0,1
    load_stage(0, 0); CP_COMMIT();
    load_stage(1, 1); CP_COMMIT();

    int cur = 0, nxt = 2;   // slot of kt, slot for kt+2
    for (int kt = 0; kt < KT; kt++) {
        asm volatile("cp.async.wait_group 1;" ::: "memory");
        __syncthreads();

        // load kt+2 into slot (kt+2)%3 == (kt-1)%3, freed by the barrier
        const int ld_kt = kt + 2;
        if (ld_kt < KT) load_stage(nxt, ld_kt);
        CP_COMMIT();

        const uint32_t baseA = sA + cur * (G_STAGE_HALFS * 2);
        const uint32_t baseB = sB + cur * (G_STAGE_HALFS * 2);
        #pragma unroll
        for (int ks = 0; ks < 4; ks++) {
            uint32_t af[4][4], bf[4][2];
            #pragma unroll
            for (int mi = 0; mi < 4; mi++) {
                uint32_t ad = baseA + 2 * ((a_row + mi * 16) * LDS + ks * 16 + a_kc);
                ldsm_x4(af[mi], ad);
            }
            #pragma unroll
            for (int pp = 0; pp < 2; pp++) {
                uint32_t r[4];
                uint32_t bd = baseB + 2 * ((b_row + pp * 16) * LDS + ks * 16 + b_kc);
                ldsm_x4(r, bd);
                bf[pp * 2][0] = r[0]; bf[pp * 2][1] = r[1];
                bf[pp * 2 + 1][0] = r[2]; bf[pp * 2 + 1][1] = r[3];
            }
            #pragma unroll
            for (int mi = 0; mi < 4; mi++)
                #pragma unroll
                for (int ni = 0; ni < 4; ni++)
                    mma_f16(acc[mi][ni], af[mi], bf[ni]);
        }
        cur = (cur == 2) ? 0 : cur + 1;
        nxt = (nxt == 2) ? 0 : nxt + 1;
    }

    // epilogue (c-frag: rows gid, gid+8; cols 2*tig, 2*tig+1)
    #pragma unroll
    for (int mi = 0; mi < 4; mi++) {
        long r0 = m0 + wm * 64 + mi * 16 + gid;
        #pragma unroll
        for (int ni = 0; ni < 4; ni++) {
            int c0 = bn * 128 + wn * 32 + ni * 8 + tig * 2;
            float bb0 = bias[c0], bb1 = bias[c0 + 1];
            #pragma unroll
            for (int h = 0; h < 2; h++) {
                long r = r0 + h * 8;
                if (r < M) {
                    float v0 = acc[mi][ni][h * 2 + 0] + bb0;
                    float v1 = acc[mi][ni][h * 2 + 1] + bb1;
                    if (MODE == 0) {
                        *reinterpret_cast<__half2*>(&g_h2[r * KW + c0]) =
                            __floats2half2_rn(fmaxf(v0, 0.f), fmaxf(v1, 0.f));
                    } else {
                        __half2 hv = __floats2half2_rn(v0, v1);
                        stg_cs32(&g_ew[r * (size_t)(WIDTH * WIDTH) + c0],
                                 *reinterpret_cast<uint32_t*>(&hv));
                    }
                }
            }
        }
    }
}

// ---------------------------------------------------------------------------
// Init: z0 = x @ fc1 + b (i < N*WIDTH) and deg = 0 (merged; independent work)
// ---------------------------------------------------------------------------
__global__ void init_kernel(const float* __restrict__ x, const float* __restrict__ w,
                            const float* __restrict__ b) {
    int i = blockIdx.x * 256 + threadIdx.x;
    if (i < N_NODES * WIDTH) g_z[i] = x[i >> 6] * w[i & 63] + b[i & 63];
    if (i < N_NODES) g_deg[i] = 0.f;
}
__global__ void deg_count(const int* __restrict__ dst) {
    int e = blockIdx.x * 256 + threadIdx.x;
    if (e < N_EDGES) atomicAdd(&g_deg[dst[e]], 1.f);
}

// ---------------------------------------------------------------------------
// zbase = z @ root_w + conv_b (also zeroes agg). 4 nodes / 256-thread block.
// ---------------------------------------------------------------------------
__global__ __launch_bounds__(256) void zbase_kernel(const float* __restrict__ rw,
                                                    const float* __restrict__ cb) {
    __shared__ float w[WIDTH * WIDTH];
    __shared__ float zs[4][WIDTH];
    const int tid = threadIdx.x;
    const int n0 = blockIdx.x * 4;
    for (int t = tid; t < WIDTH * WIDTH; t += 256) w[t] = rw[t];
    const int q = tid >> 6, o = tid & 63;
    zs[q][o] = g_z[(n0 + q) * WIDTH + o];
    __syncthreads();
    float s = cb[o];
    #pragma unroll
    for (int i = 0; i < WIDTH; i++) s += zs[q][i] * w[i * WIDTH + o];
    g_zbase[(n0 + q) * WIDTH + o] = s;
    g_agg[(n0 + q) * WIDTH + o] = 0.f;
}

// ---------------------------------------------------------------------------
// Fused: z' = relu(agg/deg + zbase); then zbase' = z' @ root_w + conv_b;
// zero agg for next iteration.
// ---------------------------------------------------------------------------
__global__ __launch_bounds__(256) void update_zbase_kernel(const float* __restrict__ rw,
                                                           const float* __restrict__ cb) {
    __shared__ float w[WIDTH * WIDTH];
    __shared__ float zs[4][WIDTH];
    const int tid = threadIdx.x;
    const int n0 = blockIdx.x * 4;
    for (int t = tid; t < WIDTH * WIDTH; t += 256) w[t] = rw[t];
    const int q = tid >> 6, o = tid & 63;
    const int n = n0 + q;
    const float d = fmaxf(g_deg[n], 1.f);
    const float znew = fmaxf(g_agg[n * WIDTH + o] / d + g_zbase[n * WIDTH + o], 0.f);
    g_z[n * WIDTH + o] = znew;
    zs[q][o] = znew;
    __syncthreads();
    float s = cb[o];
    #pragma unroll
    for (int i = 0; i < WIDTH; i++) s += zs[q][i] * w[i * WIDTH + o];
    g_zbase[n * WIDTH + o] = s;
    g_agg[n * WIDTH + o] = 0.f;
}

// ---------------------------------------------------------------------------
// Final z = relu(agg/deg + zbase)
// ---------------------------------------------------------------------------
__global__ void update_kernel() {
    int i = blockIdx.x * 256 + threadIdx.x;
    if (i < N_NODES * WIDTH) {
        float d = fmaxf(g_deg[i >> 6], 1.f);
        g_z[i] = fmaxf(g_agg[i] / d + g_zbase[i], 0.f);
    }
}

// ---------------------------------------------------------------------------
// Message + scatter: one warp per edge. msg = z[src] @ ew[e] (64x64 fp16),
// fp32 accumulate, atomic scatter into agg[dst].
// EXACT R8/R13 configuration (best measured): zero-skip, 8-wide chunked
// gather, two 32-bit masks, plain loads. Low regs keep occupancy high;
// warps/SM x MLP is the product that matters.
// ---------------------------------------------------------------------------
__global__ __launch_bounds__(256) void msg_kernel(const int* __restrict__ src,
                                                  const int* __restrict__ dst) {
    const int e = blockIdx.x * 8 + (threadIdx.x >> 5);
    if (e >= N_EDGES) return;
    const int lane = threadIdx.x & 31;
    const int s = src[e];
    const float z0 = g_z[s * WIDTH + lane];
    const float z1 = g_z[s * WIDTH + 32 + lane];
    uint32_t m0 = __ballot_sync(0xffffffffu, z0 != 0.f);
    uint32_t m1 = __ballot_sync(0xffffffffu, z1 != 0.f);
    const __half2* row = reinterpret_cast<const __half2*>(g_ew) + (size_t)e * 2048 + lane;
    float a0 = 0.f, a1 = 0.f;

    #pragma unroll
    for (int half_sel = 0; half_sel < 2; half_sel++) {
        uint32_t m = half_sel ? m1 : m0;
        const float zv = half_sel ? z1 : z0;
        const int base = half_sel ? 32 : 0;
        while (m) {
            int idx[8];
            #pragma unroll
            for (int u = 0; u < 8; u++) {
                if (m) { idx[u] = __ffs(m) - 1; m &= m - 1; }
                else     idx[u] = -1;
            }
            float2 w[8];
            #pragma unroll
            for (int u = 0; u < 8; u++)
                if (idx[u] >= 0) w[u] = __half22float2(row[(idx[u] + base) * 32]);
            #pragma unroll
            for (int u = 0; u < 8; u++) {
                if (idx[u] >= 0) {
                    float zi = __shfl_sync(0xffffffffu, zv, idx[u]);
                    a0 = fmaf(zi, w[u].x, a0);
                    a1 = fmaf(zi, w[u].y, a1);
                }
            }
        }
    }

    const int d = dst[e];
    atomicAdd(&g_agg[d * WIDTH + lane * 2],     a0);
    atomicAdd(&g_agg[d * WIDTH + lane * 2 + 1], a1);
}

// ---------------------------------------------------------------------------
// out = z @ fc2_w + fc2_b : warp per node
// ---------------------------------------------------------------------------
__global__ __launch_bounds__(256) void out_kernel(const float* __restrict__ w,
                                                  const float* __restrict__ b,
                                                  float* __restrict__ out) {
    const int n = blockIdx.x * 8 + (threadIdx.x >> 5);
    const int lane = threadIdx.x & 31;
    if (n >= N_NODES) return;
    float s = g_z[n * WIDTH + lane] * w[lane] + g_z[n * WIDTH + 32 + lane] * w[32 + lane];
    #pragma unroll
    for (int off = 16; off; off >>= 1) s += __shfl_xor_sync(0xffffffffu, s, off);
    if (lane == 0) out[n] = s + b[0];
}

// ---------------------------------------------------------------------------
// Launch
// ---------------------------------------------------------------------------
extern "C" void kernel_launch(void* const* d_in, const int* in_sizes, int n_in,
                              void* d_out, int out_size) {
    const float* x      = (const float*)d_in[0];
    const int*   ei     = (const int*)  d_in[1];
    const float* ea     = (const float*)d_in[2];
    const float* fc1_w  = (const float*)d_in[3];
    const float* fc1_b  = (const float*)d_in[4];
    const float* k1_w   = (const float*)d_in[5];
    const float* k1_b   = (const float*)d_in[6];
    const float* k2_w   = (const float*)d_in[7];
    const float* k2_b   = (const float*)d_in[8];
    const float* k3_w   = (const float*)d_in[9];
    const float* k3_b   = (const float*)d_in[10];
    const float* root_w = (const float*)d_in[11];
    const float* conv_b = (const float*)d_in[12];
    const float* fc2_w  = (const float*)d_in[13];
    const float* fc2_b  = (const float*)d_in[14];
    const int* src = ei;
    const int* dst = ei + N_EDGES;
    float* out = (float*)d_out;

    __half* k2t_p; cudaGetSymbolAddress((void**)&k2t_p, g_k2t);
    __half* k3t_p; cudaGetSymbolAddress((void**)&k3t_p, g_k3t);

    cudaFuncSetAttribute(gemm_f16<0>, cudaFuncAttributeMaxDynamicSharedMemorySize, G_SMEM_BYTES);
    cudaFuncSetAttribute(gemm_f16<1>, cudaFuncAttributeMaxDynamicSharedMemorySize, G_SMEM_BYTES);

    transpose_h<<<dim3(32, 32),  dim3(32, 8)>>>(k2_w, k2t_p, KW, KW);
    transpose_h<<<dim3(32, 128), dim3(32, 8)>>>(k3_w, k3t_p, KW, WIDTH * WIDTH);
    h1_kernel<<<N_EDGES / 16, 256>>>(ea, k1_w, k1_b);
    gemm_f16<0><<<dim3(KW / 128, (N_EDGES + 127) / 128), 256, G_SMEM_BYTES>>>(k2_b);
    gemm_f16<1><<<dim3((WIDTH * WIDTH) / 128, (N_EDGES + 127) / 128), 256, G_SMEM_BYTES>>>(k3_b);
    init_kernel<<<(N_NODES * WIDTH) / 256, 256>>>(x, fc1_w, fc1_b);
    deg_count<<<(N_EDGES + 255) / 256, 256>>>(dst);
    zbase_kernel<<<N_NODES / 4, 256>>>(root_w, conv_b);
    for (int it = 0; it < DEPTH; it++) {
        msg_kernel<<<(N_EDGES + 7) / 8, 256>>>(src, dst);
        if (it < DEPTH - 1)
            update_zbase_kernel<<<N_NODES / 4, 256>>>(root_w, conv_b);
        else
            update_kernel<<<(N_NODES * WIDTH) / 256, 256>>>();
    }
    out_kernel<<<(N_NODES + 7) / 8, 256>>>(fc2_w, fc2_b, out);
}